// round 2
// baseline (speedup 1.0000x reference)
#include <cuda_runtime.h>
#include <cstdint>

#define PITCH 68
#define NTHR  256

// ---------------- persistent device scratch (static, no allocations) ----------------
__device__ __align__(16) float g_W1T[784*128];
__device__ __align__(16) float g_M1T[128*128];   // -(W1@fb1)^T, k-major
__device__ __align__(16) float g_U1T[128*128];
__device__ __align__(16) float g_W2T[128*64];
__device__ __align__(16) float g_M2T[64*64];     // negated
__device__ __align__(16) float g_U2T[64*64];
__device__ __align__(16) float g_W3T[64*32];
__device__ __align__(16) float g_M3T[32*32];     // negated
__device__ __align__(16) float g_U3T[32*32];
__device__ __align__(16) float g_c1[128];
__device__ __align__(16) float g_c2[64];
__device__ __align__(16) float g_c3[32];

// ---------------- helpers ----------------
__device__ __forceinline__ unsigned long long dup2(float x) {
    unsigned long long r;
    asm("mov.b64 %0, {%1, %1};" : "=l"(r) : "f"(x));
    return r;
}
__device__ __forceinline__ void up2(unsigned long long v, float &lo, float &hi) {
    asm("mov.b64 {%0, %1}, %2;" : "=f"(lo), "=f"(hi) : "l"(v));
}
__device__ __forceinline__ void fma2(unsigned long long &d, unsigned long long a, unsigned long long b) {
    asm("fma.rn.f32x2 %0, %1, %2, %0;" : "+l"(d) : "l"(a), "l"(b));
}
// tanh(x) = 1 - 2/(1 + e^{2x}) via MUFU.EX2 + MUFU.RCP  (~1e-6 abs err)
__device__ __forceinline__ float ftanh(float x) {
    float e, r;
    asm("ex2.approx.ftz.f32 %0, %1;" : "=f"(e) : "f"(x * 2.8853900817779268f));
    asm("rcp.approx.ftz.f32 %0, %1;" : "=f"(r) : "f"(e + 1.0f));
    return fmaf(-2.0f, r, 1.0f);
}

// register-tile GEMM: A feature-major [K][PITCH] (smem), B k-major [K][LDB]
// thread computes 4 rows (i0..i0+3) x 2*NP cols (j0..), f32x2 accumulators
template<int K, int NP, int LDB>
__device__ __forceinline__ void gemm_fm(const float* __restrict__ A,
                                        const float* __restrict__ B,
                                        int i0, int j0,
                                        unsigned long long (&acc)[4][NP]) {
#pragma unroll 8
    for (int k = 0; k < K; k++) {
        float4 a4 = *reinterpret_cast<const float4*>(A + k * PITCH + i0);
        const float* br = B + k * LDB + j0;
        unsigned long long b[NP];
#pragma unroll
        for (int p = 0; p < NP; p++)
            b[p] = *reinterpret_cast<const unsigned long long*>(br + 2 * p);
        unsigned long long A0 = dup2(a4.x), A1 = dup2(a4.y), A2 = dup2(a4.z), A3 = dup2(a4.w);
#pragma unroll
        for (int p = 0; p < NP; p++) {
            fma2(acc[0][p], A0, b[p]);
            fma2(acc[1][p], A1, b[p]);
            fma2(acc[2][p], A2, b[p]);
            fma2(acc[3][p], A3, b[p]);
        }
    }
}

// ---------------- prep kernels ----------------
__global__ void prep_transpose(const float* __restrict__ W1w, const float* __restrict__ U1w,
                               const float* __restrict__ W2w, const float* __restrict__ U2w,
                               const float* __restrict__ W3w, const float* __restrict__ U3w) {
    int idx = blockIdx.x * blockDim.x + threadIdx.x;
    int stride = gridDim.x * blockDim.x;
    for (int t = idx; t < 784 * 128; t += stride) {          // W1T[k][j] = W1[j][k]
        int k = t >> 7, j = t & 127;
        g_W1T[t] = W1w[j * 784 + k];
    }
    for (int t = idx; t < 128 * 128; t += stride) {          // U1T
        int k = t >> 7, j = t & 127;
        g_U1T[t] = U1w[j * 128 + k];
    }
    for (int t = idx; t < 128 * 64; t += stride) {           // W2T [128][64]
        int k = t >> 6, j = t & 63;
        g_W2T[t] = W2w[j * 128 + k];
    }
    for (int t = idx; t < 64 * 64; t += stride) {            // U2T
        int k = t >> 6, j = t & 63;
        g_U2T[t] = U2w[j * 64 + k];
    }
    for (int t = idx; t < 64 * 32; t += stride) {            // W3T [64][32]
        int k = t >> 5, j = t & 31;
        g_W3T[t] = W3w[j * 64 + k];
    }
    for (int t = idx; t < 32 * 32; t += stride) {            // U3T
        int k = t >> 5, j = t & 31;
        g_U3T[t] = U3w[j * 32 + k];
    }
}

__global__ void prep_fuse(const float* __restrict__ W1w, const float* __restrict__ fb1w,
                          const float* __restrict__ W1b, const float* __restrict__ fb1b,
                          const float* __restrict__ W2w, const float* __restrict__ fb2w,
                          const float* __restrict__ W2b, const float* __restrict__ fb2b,
                          const float* __restrict__ W3w, const float* __restrict__ fb3w,
                          const float* __restrict__ W3b, const float* __restrict__ fb3b) {
    int idx = blockIdx.x * blockDim.x + threadIdx.x;
    int stride = gridDim.x * blockDim.x;
    // M1 = W1@fb1 -> store negated transpose [k][j]
    for (int t = idx; t < 128 * 128; t += stride) {
        int j = t >> 7, k = t & 127;
        float s = 0.f;
#pragma unroll 4
        for (int d = 0; d < 784; d++) s += W1w[j * 784 + d] * fb1w[d * 128 + k];
        g_M1T[k * 128 + j] = -s;
    }
    for (int t = idx; t < 64 * 64; t += stride) {
        int j = t >> 6, k = t & 63;
        float s = 0.f;
#pragma unroll 4
        for (int d = 0; d < 128; d++) s += W2w[j * 128 + d] * fb2w[d * 64 + k];
        g_M2T[k * 64 + j] = -s;
    }
    for (int t = idx; t < 32 * 32; t += stride) {
        int j = t >> 5, k = t & 31;
        float s = 0.f;
#pragma unroll 4
        for (int d = 0; d < 64; d++) s += W3w[j * 64 + d] * fb3w[d * 32 + k];
        g_M3T[k * 32 + j] = -s;
    }
    // bias folds: c = W_b - W @ fb_b
    for (int j = idx; j < 128; j += stride) {
        float s = W1b[j];
#pragma unroll 4
        for (int d = 0; d < 784; d++) s -= W1w[j * 784 + d] * fb1b[d];
        g_c1[j] = s;
    }
    for (int j = idx; j < 64; j += stride) {
        float s = W2b[j];
#pragma unroll 4
        for (int d = 0; d < 128; d++) s -= W2w[j * 128 + d] * fb2b[d];
        g_c2[j] = s;
    }
    for (int j = idx; j < 32; j += stride) {
        float s = W3b[j];
#pragma unroll 4
        for (int d = 0; d < 64; d++) s -= W3w[j * 64 + d] * fb3b[d];
        g_c3[j] = s;
    }
}

// ---------------- main persistent-tile kernel ----------------
// smem layout (floats):
//   h1s [128][68] @ 0        (8704)
//   xws [128][68] @ 8704     (8704)
//   h2s [ 64][68] @ 17408    (4352)
//   h3s [ 32][68] @ 21760    (2176)
//   wbuf          @ 23936    (32768)   = sM1[128*128] + sU1[128*128]
//                                       (phase1: x staging [64][396] = 25344)
// total = 56704 floats = 226816 bytes
__global__ void __launch_bounds__(NTHR, 1)
pcnet_main(const float* __restrict__ x,
           const float* __restrict__ U1b, const float* __restrict__ U2b,
           const float* __restrict__ U3b,
           const float* __restrict__ clfw, const float* __restrict__ clfb,
           const int* __restrict__ steps_p,
           float* __restrict__ out) {
    extern __shared__ float sm[];
    float* h1s  = sm;
    float* xws  = sm + 128 * PITCH;
    float* h2s  = xws + 128 * PITCH;
    float* h3s  = h2s + 64 * PITCH;
    float* wbuf = h3s + 32 * PITCH;
    float* sM1  = wbuf;
    float* sU1  = wbuf + 128 * 128;
    float* xst  = wbuf;              // phase-1 overlay: [64][396]

    const int tid  = threadIdx.x;
    const int row0 = blockIdx.x * 64;
    const int iIdx = tid >> 4;
    const int jIdx = tid & 15;
    const int i0   = iIdx * 4;

    // zero states (padding included)
    for (int i = tid; i < 128 * PITCH; i += NTHR) h1s[i] = 0.f;
    for (int i = tid; i <  64 * PITCH; i += NTHR) h2s[i] = 0.f;
    for (int i = tid; i <  32 * PITCH; i += NTHR) h3s[i] = 0.f;

    int steps = *steps_p;
    if (steps < 0 || steps > 64) steps = 5;

    // ---- phase 1: xw = x @ W1^T + c1 ----
    {
        const int j0 = jIdx * 8;
        unsigned long long acc[4][4] = {};
        for (int c = 0; c < 2; c++) {
            __syncthreads();
            // stage 64 rows x 392 cols of x into smem (row-major, pitch 396)
            for (int idx = tid; idx < 64 * 98; idx += NTHR) {
                int r = idx / 98, c4 = idx - r * 98;
                float4 v = *reinterpret_cast<const float4*>(
                    x + (size_t)(row0 + r) * 784 + c * 392 + c4 * 4);
                *reinterpret_cast<float4*>(xst + r * 396 + c4 * 4) = v;
            }
            __syncthreads();
            const float* Bb = g_W1T + c * 392 * 128;
#pragma unroll 4
            for (int kk = 0; kk < 392; kk++) {
                const float* br = Bb + kk * 128 + j0;
                unsigned long long b[4];
#pragma unroll
                for (int p = 0; p < 4; p++)
                    b[p] = *reinterpret_cast<const unsigned long long*>(br + 2 * p);
                unsigned long long A0 = dup2(xst[(i0 + 0) * 396 + kk]);
                unsigned long long A1 = dup2(xst[(i0 + 1) * 396 + kk]);
                unsigned long long A2 = dup2(xst[(i0 + 2) * 396 + kk]);
                unsigned long long A3 = dup2(xst[(i0 + 3) * 396 + kk]);
#pragma unroll
                for (int p = 0; p < 4; p++) {
                    fma2(acc[0][p], A0, b[p]);
                    fma2(acc[1][p], A1, b[p]);
                    fma2(acc[2][p], A2, b[p]);
                    fma2(acc[3][p], A3, b[p]);
                }
            }
        }
        // write xw (+c1), feature-major
#pragma unroll
        for (int p = 0; p < 4; p++) {
            int j = j0 + 2 * p;
            float cc0 = g_c1[j], cc1 = g_c1[j + 1];
#pragma unroll
            for (int r = 0; r < 4; r++) {
                float v0, v1;
                up2(acc[r][p], v0, v1);
                xws[j * PITCH + i0 + r]       = v0 + cc0;
                xws[(j + 1) * PITCH + i0 + r] = v1 + cc1;
            }
        }
    }
    __syncthreads();   // all xst reads done -> safe to overwrite wbuf
    for (int i = tid; i < 128 * 128; i += NTHR) {
        sM1[i] = g_M1T[i];
        sU1[i] = g_U1T[i];
    }
    __syncthreads();

    // ---- step loop ----
    for (int s = 0; s < steps; s++) {
        // --- L3: h3 += tanh(h2@W3T - h3@M3T + c3) + tanh(h3@U3T + U3b) ---
        {
            const int j0 = jIdx * 2;
            unsigned long long aW[4][1] = {}, aM[4][1] = {}, aU[4][1] = {};
            gemm_fm<64, 1, 32>(h2s, g_W3T, i0, j0, aW);
            gemm_fm<32, 1, 32>(h3s, g_M3T, i0, j0, aM);
            gemm_fm<32, 1, 32>(h3s, g_U3T, i0, j0, aU);
            float cc0 = g_c3[j0], cc1 = g_c3[j0 + 1];
            float ub0 = U3b[j0],  ub1 = U3b[j0 + 1];
            __syncthreads();
#pragma unroll
            for (int r = 0; r < 4; r++) {
                float w0, w1, m0, m1, u0, u1;
                up2(aW[r][0], w0, w1);
                up2(aM[r][0], m0, m1);
                up2(aU[r][0], u0, u1);
                int id = j0 * PITCH + i0 + r;
                h3s[id]         += ftanh(w0 + m0 + cc0) + ftanh(u0 + ub0);
                h3s[id + PITCH] += ftanh(w1 + m1 + cc1) + ftanh(u1 + ub1);
            }
            __syncthreads();
        }
        // --- L2: h2 += tanh(h1@W2T - h2@M2T + c2) + tanh(h2@U2T + U2b) ---
        {
            const int j0 = jIdx * 4;
            unsigned long long aW[4][2] = {}, aM[4][2] = {}, aU[4][2] = {};
            gemm_fm<128, 2, 64>(h1s, g_W2T, i0, j0, aW);
            gemm_fm< 64, 2, 64>(h2s, g_M2T, i0, j0, aM);
            gemm_fm< 64, 2, 64>(h2s, g_U2T, i0, j0, aU);
            __syncthreads();
#pragma unroll
            for (int p = 0; p < 2; p++) {
                int j = j0 + 2 * p;
                float cc0 = g_c2[j], cc1 = g_c2[j + 1];
                float ub0 = U2b[j],  ub1 = U2b[j + 1];
#pragma unroll
                for (int r = 0; r < 4; r++) {
                    float w0, w1, m0, m1, u0, u1;
                    up2(aW[r][p], w0, w1);
                    up2(aM[r][p], m0, m1);
                    up2(aU[r][p], u0, u1);
                    int id = j * PITCH + i0 + r;
                    h2s[id]         += ftanh(w0 + m0 + cc0) + ftanh(u0 + ub0);
                    h2s[id + PITCH] += ftanh(w1 + m1 + cc1) + ftanh(u1 + ub1);
                }
            }
            __syncthreads();
        }
        // --- L1: h1 += tanh(xw - h1@M1T) + tanh(h1@U1T + U1b) ---
        {
            const int j0 = jIdx * 8;
            unsigned long long aM[4][4] = {}, aU[4][4] = {};
            gemm_fm<128, 4, 128>(h1s, sM1, i0, j0, aM);
            gemm_fm<128, 4, 128>(h1s, sU1, i0, j0, aU);
            __syncthreads();
#pragma unroll
            for (int p = 0; p < 4; p++) {
                int j = j0 + 2 * p;
                float ub0 = U1b[j], ub1 = U1b[j + 1];
#pragma unroll
                for (int r = 0; r < 4; r++) {
                    float m0, m1, u0, u1;
                    up2(aM[r][p], m0, m1);
                    up2(aU[r][p], u0, u1);
                    int id = j * PITCH + i0 + r;
                    h1s[id]         += ftanh(xws[id] + m0)         + ftanh(u0 + ub0);
                    h1s[id + PITCH] += ftanh(xws[id + PITCH] + m1) + ftanh(u1 + ub1);
                }
            }
            __syncthreads();
        }
    }

    // ---- classifier: out = h3 @ clf^T + clf_b ----
    for (int idx = tid; idx < 64 * 10; idx += NTHR) {
        int r = idx / 10, cc = idx - r * 10;
        float s = clfb[cc];
#pragma unroll
        for (int k = 0; k < 32; k++) s += h3s[k * PITCH + r] * clfw[cc * 32 + k];
        out[(size_t)(row0 + r) * 10 + cc] = s;
    }
}

// ---------------- launch ----------------
extern "C" void kernel_launch(void* const* d_in, const int* in_sizes, int n_in,
                              void* d_out, int out_size) {
    const float* x    = (const float*)d_in[0];
    const float* W1w  = (const float*)d_in[1];
    const float* W1b  = (const float*)d_in[2];
    const float* U1w  = (const float*)d_in[3];
    const float* U1b  = (const float*)d_in[4];
    const float* W2w  = (const float*)d_in[5];
    const float* W2b  = (const float*)d_in[6];
    const float* U2w  = (const float*)d_in[7];
    const float* U2b  = (const float*)d_in[8];
    const float* W3w  = (const float*)d_in[9];
    const float* W3b  = (const float*)d_in[10];
    const float* U3w  = (const float*)d_in[11];
    const float* U3b  = (const float*)d_in[12];
    const float* fb3w = (const float*)d_in[13];
    const float* fb3b = (const float*)d_in[14];
    const float* fb2w = (const float*)d_in[15];
    const float* fb2b = (const float*)d_in[16];
    const float* fb1w = (const float*)d_in[17];
    const float* fb1b = (const float*)d_in[18];
    const float* clfw = (const float*)d_in[19];
    const float* clfb = (const float*)d_in[20];
    const int*   stp  = (const int*)d_in[21];

    int B = in_sizes[0] / 784;

    prep_transpose<<<256, 256>>>(W1w, U1w, W2w, U2w, W3w, U3w);
    prep_fuse<<<128, 256>>>(W1w, fb1w, W1b, fb1b,
                            W2w, fb2w, W2b, fb2b,
                            W3w, fb3w, W3b, fb3b);

    const int smem_bytes = 56704 * 4;   // 226816
    cudaFuncSetAttribute(pcnet_main, cudaFuncAttributeMaxDynamicSharedMemorySize, smem_bytes);
    pcnet_main<<<B / 64, NTHR, smem_bytes>>>(x, U1b, U2b, U3b, clfw, clfb, stp, (float*)d_out);
}